// round 2
// baseline (speedup 1.0000x reference)
#include <cuda_runtime.h>
#include <cstdint>

#define BB   2048
#define SSQ  512
#define H2   64
#define SC   128     // seq chunk
#define NCH  4       // 512/128
#define ESTR 132     // encT row stride (pad: conflict-free staging + float4 loads)

__device__ __forceinline__ uint64_t pk2(float x, float y) {
    uint64_t r; asm("mov.b64 %0, {%1, %2};" : "=l"(r) : "f"(x), "f"(y)); return r;
}
__device__ __forceinline__ void upk2(uint64_t v, float& x, float& y) {
    asm("mov.b64 {%0, %1}, %2;" : "=f"(x), "=f"(y) : "l"(v));
}
__device__ __forceinline__ void ffma2(uint64_t& d, uint64_t a, uint64_t b) {
    asm("fma.rn.f32x2 %0, %1, %2, %0;" : "+l"(d) : "l"(a), "l"(b));
}
__device__ __forceinline__ float tanh_ap(float x) {
    float y; asm("tanh.approx.f32 %0, %1;" : "=f"(y) : "f"(x)); return y;
}
__device__ __forceinline__ float sigm(float x) { return 1.0f / (1.0f + __expf(-x)); }

__global__ __launch_bounds__(256) void decoder_fused_kernel(
    const float* __restrict__ dec_in, const float* __restrict__ s_in,
    const float* __restrict__ enc,    const float* __restrict__ W_attn,
    const float* __restrict__ b_attn, const float* __restrict__ v_attn,
    const float* __restrict__ W_emb,  const float* __restrict__ b_emb,
    const float* __restrict__ W_ih,   const float* __restrict__ W_hh,
    const float* __restrict__ b_ih,   const float* __restrict__ b_hh,
    const float* __restrict__ W_fc,   const float* __restrict__ b_fc,
    float* __restrict__ out, int write_h)
{
    __shared__ float encT[64 * ESTR];     // [k][s] transposed enc chunk
    __shared__ float WeT [64 * 32];       // [k][j] transposed attention enc-weights
    __shared__ float part[8 * 128];       // per-warp-row logit partials
    __shared__ float psm [128];           // exp(logit - m) per chunk
    __shared__ float red [8];
    __shared__ float ctxa[64];            // running (rescaled) context accumulator
    __shared__ float s_sm[32], pre_sm[32], v_sm[32];
    __shared__ float gh_sm[96], gie_sm[96], emb_sm[16];
    __shared__ float smisc[4];            // 0: m_run, 1: l_run, 2: scale_old

    const int t    = threadIdx.x;
    const int b    = blockIdx.x;
    const int lane = t & 31;
    const int w    = t >> 5;     // warp id
    const int tx   = t & 31;     // s-tile index (s0 = 4*tx)
    const int ty   = t >> 5;     // j-tile index (j0 = 4*ty)

    // ---------------- per-b init ----------------
    if (t < 32) s_sm[t] = s_in[b * 32 + t];
    if (t < 16) {
        float x = dec_in[b];
        float e = W_emb[t] * x + b_emb[t];
        emb_sm[t] = e > 0.f ? e : 0.f;
    }
    if (t < 64) ctxa[t] = 0.f;
    if (t == 0) { smisc[0] = -1e30f; smisc[1] = 0.f; smisc[2] = 0.f; }
    for (int idx = t; idx < 2048; idx += 256) {
        int k = idx >> 5, j = idx & 31;
        WeT[idx] = W_attn[j * 96 + 32 + k];   // enc-columns of W_attn
    }
    __syncthreads();

    if (t < 32) {
        float a = b_attn[t];
        #pragma unroll
        for (int m = 0; m < 32; ++m) a += W_attn[t * 96 + m] * s_sm[m];
        pre_sm[t] = a;
        v_sm[t]   = v_attn[t];
    } else if (t < 128) {
        int g = t - 32;                       // 0..95
        float a = b_hh[g];
        #pragma unroll
        for (int m = 0; m < 32; ++m) a += W_hh[g * 32 + m] * s_sm[m];
        gh_sm[g] = a;
    } else if (t < 224) {
        int g = t - 128;                      // 0..95
        float a = b_ih[g];
        #pragma unroll
        for (int m = 0; m < 16; ++m) a += W_ih[g * 80 + m] * emb_sm[m];
        gie_sm[g] = a;
    }

    // ---------------- main loop over seq chunks ----------------
    float lg = 0.f;
    for (int ch = 0; ch < NCH; ++ch) {
        __syncthreads();   // prior ctx-phase reads of encT done; init done (ch==0)

        // stage enc chunk, transposed to k-major (conflict-free stores)
        #pragma unroll
        for (int it = 0; it < 8; ++it) {
            int lin = it * 256 + t;
            int s   = lin & 127;
            int q   = lin >> 7;
            const float4 vv = *reinterpret_cast<const float4*>(
                enc + ((size_t)((ch * SC + s) * BB + b)) * 64 + 4 * q);
            float* dst = &encT[s];
            dst[(4 * q + 0) * ESTR] = vv.x;
            dst[(4 * q + 1) * ESTR] = vv.y;
            dst[(4 * q + 2) * ESTR] = vv.z;
            dst[(4 * q + 3) * ESTR] = vv.w;
        }
        __syncthreads();

        // micro-GEMM: E[32j x 128s] = WeT^T * encT, 4x4 tile per thread, FFMA2
        uint64_t acc[4][2];
        #pragma unroll
        for (int a = 0; a < 4; ++a) { acc[a][0] = 0ull; acc[a][1] = 0ull; }
        #pragma unroll 16
        for (int k = 0; k < 64; ++k) {
            float4 wv = *reinterpret_cast<const float4*>(&WeT[k * 32 + 4 * ty]);
            float4 ev = *reinterpret_cast<const float4*>(&encT[k * ESTR + 4 * tx]);
            uint64_t e01 = pk2(ev.x, ev.y);
            uint64_t e23 = pk2(ev.z, ev.w);
            uint64_t w0 = pk2(wv.x, wv.x); ffma2(acc[0][0], w0, e01); ffma2(acc[0][1], w0, e23);
            uint64_t w1 = pk2(wv.y, wv.y); ffma2(acc[1][0], w1, e01); ffma2(acc[1][1], w1, e23);
            uint64_t w2 = pk2(wv.z, wv.z); ffma2(acc[2][0], w2, e01); ffma2(acc[2][1], w2, e23);
            uint64_t w3 = pk2(wv.w, wv.w); ffma2(acc[3][0], w3, e01); ffma2(acc[3][1], w3, e23);
        }

        // epilogue: tanh + v-dot partials
        float4 pre4 = *reinterpret_cast<const float4*>(&pre_sm[4 * ty]);
        float4 vv4  = *reinterpret_cast<const float4*>(&v_sm[4 * ty]);
        float pre[4] = {pre4.x, pre4.y, pre4.z, pre4.w};
        float vj [4] = {vv4.x, vv4.y, vv4.z, vv4.w};
        float pl0 = 0.f, pl1 = 0.f, pl2 = 0.f, pl3 = 0.f;
        #pragma unroll
        for (int a = 0; a < 4; ++a) {
            float x0, x1, x2, x3;
            upk2(acc[a][0], x0, x1);
            upk2(acc[a][1], x2, x3);
            pl0 += vj[a] * tanh_ap(x0 + pre[a]);
            pl1 += vj[a] * tanh_ap(x1 + pre[a]);
            pl2 += vj[a] * tanh_ap(x2 + pre[a]);
            pl3 += vj[a] * tanh_ap(x3 + pre[a]);
        }
        *reinterpret_cast<float4*>(&part[ty * 128 + 4 * tx]) = make_float4(pl0, pl1, pl2, pl3);
        __syncthreads();

        // logits + chunk max
        if (t < 128) {
            lg = part[t];
            #pragma unroll
            for (int r2 = 1; r2 < 8; ++r2) lg += part[r2 * 128 + t];
            float wm = lg;
            #pragma unroll
            for (int off = 16; off > 0; off >>= 1)
                wm = fmaxf(wm, __shfl_xor_sync(0xffffffffu, wm, off));
            if (lane == 0) red[w] = wm;
        }
        __syncthreads();
        if (t == 0) {
            float cm = fmaxf(fmaxf(red[0], red[1]), fmaxf(red[2], red[3]));
            float mo = smisc[0];
            float mn = fmaxf(mo, cm);
            smisc[2] = __expf(mo - mn);     // scale for old accumulators (0 on first chunk)
            smisc[0] = mn;
        }
        __syncthreads();
        float mn = smisc[0];
        if (t < 128) {
            float p = __expf(lg - mn);
            psm[t] = p;
            float ws = p;
            #pragma unroll
            for (int off = 16; off > 0; off >>= 1)
                ws += __shfl_xor_sync(0xffffffffu, ws, off);
            if (lane == 0) red[w] = ws;
        }
        __syncthreads();
        if (t == 0) smisc[1] = smisc[1] * smisc[2] + (red[0] + red[1] + red[2] + red[3]);

        // context accumulation: warp w owns h in [8w, 8w+8)
        float4 pq = *reinterpret_cast<const float4*>(&psm[4 * lane]);
        float ps[8];
        #pragma unroll
        for (int hh = 0; hh < 8; ++hh) {
            float4 ev = *reinterpret_cast<const float4*>(&encT[(w * 8 + hh) * ESTR + 4 * lane]);
            ps[hh] = pq.x * ev.x + pq.y * ev.y + pq.z * ev.z + pq.w * ev.w;
        }
        #pragma unroll
        for (int off = 16; off > 0; off >>= 1) {
            #pragma unroll
            for (int hh = 0; hh < 8; ++hh)
                ps[hh] += __shfl_xor_sync(0xffffffffu, ps[hh], off);
        }
        if (lane == 0) {
            float sc = smisc[2];
            #pragma unroll
            for (int hh = 0; hh < 8; ++hh)
                ctxa[w * 8 + hh] = ctxa[w * 8 + hh] * sc + ps[hh];
        }
    }

    // ---------------- finalize: ctx, GRU, fc ----------------
    __syncthreads();
    if (t < 64) ctxa[t] = ctxa[t] / smisc[1];
    __syncthreads();

    if (w == 0) {
        int j = lane;
        float gir = gie_sm[j], giz = gie_sm[32 + j], gin = gie_sm[64 + j];
        const float* wr = W_ih + j        * 80 + 16;
        const float* wz = W_ih + (32 + j) * 80 + 16;
        const float* wn = W_ih + (64 + j) * 80 + 16;
        #pragma unroll 8
        for (int k2 = 0; k2 < 64; ++k2) {
            float c = ctxa[k2];
            gir += wr[k2] * c;
            giz += wz[k2] * c;
            gin += wn[k2] * c;
        }
        float r = sigm(gir + gh_sm[j]);
        float z = sigm(giz + gh_sm[32 + j]);
        float n = tanhf(gin + r * gh_sm[64 + j]);
        float h = (1.f - z) * n + z * s_sm[j];
        if (write_h) out[BB + b * 32 + j] = h;

        float contrib = h * W_fc[j]
                      + ctxa[2 * j]     * W_fc[32 + 2 * j]
                      + ctxa[2 * j + 1] * W_fc[33 + 2 * j];
        if (j < 16) contrib += emb_sm[j] * W_fc[96 + j];
        #pragma unroll
        for (int off = 16; off > 0; off >>= 1)
            contrib += __shfl_xor_sync(0xffffffffu, contrib, off);
        if (j == 0) out[b] = contrib + b_fc[0];
    }
}

extern "C" void kernel_launch(void* const* d_in, const int* in_sizes, int n_in,
                              void* d_out, int out_size) {
    const float* dec_in = (const float*)d_in[0];
    const float* s_in   = (const float*)d_in[1];
    const float* enc    = (const float*)d_in[2];
    const float* W_attn = (const float*)d_in[3];
    const float* b_attn = (const float*)d_in[4];
    const float* v_attn = (const float*)d_in[5];
    const float* W_emb  = (const float*)d_in[6];
    const float* b_emb  = (const float*)d_in[7];
    const float* W_ih   = (const float*)d_in[8];
    const float* W_hh   = (const float*)d_in[9];
    const float* b_ih   = (const float*)d_in[10];
    const float* b_hh   = (const float*)d_in[11];
    const float* W_fc   = (const float*)d_in[12];
    const float* b_fc   = (const float*)d_in[13];

    int write_h = (out_size >= BB * 33) ? 1 : 0;
    decoder_fused_kernel<<<BB, 256>>>(dec_in, s_in, enc, W_attn, b_attn, v_attn,
                                      W_emb, b_emb, W_ih, W_hh, b_ih, b_hh,
                                      W_fc, b_fc, (float*)d_out, write_h);
}

// round 4
// speedup vs baseline: 1.6119x; 1.6119x over previous
#include <cuda_runtime.h>
#include <cstdint>

#define BB 2048
#define ASTR 68          // A smem row stride in words (64 + 4 pad)
#define BSTR 36          // B smem row stride in words (32 + 4 pad)

__device__ __forceinline__ uint32_t f2tf32(float x) {
    uint32_t r; asm("cvt.rna.tf32.f32 %0, %1;" : "=r"(r) : "f"(x)); return r;
}
__device__ __forceinline__ float tanh_ap(float x) {
    float y; asm("tanh.approx.f32 %0, %1;" : "=f"(y) : "f"(x)); return y;
}
__device__ __forceinline__ float sigm(float x) { return 1.0f / (1.0f + __expf(-x)); }

__device__ __forceinline__ void mma_tf32(float* d, const uint32_t* a, const uint32_t* bb) {
    asm volatile(
        "mma.sync.aligned.m16n8k8.row.col.f32.tf32.tf32.f32 "
        "{%0,%1,%2,%3}, {%4,%5,%6,%7}, {%8,%9}, {%0,%1,%2,%3};"
        : "+f"(d[0]), "+f"(d[1]), "+f"(d[2]), "+f"(d[3])
        : "r"(a[0]), "r"(a[1]), "r"(a[2]), "r"(a[3]), "r"(bb[0]), "r"(bb[1]));
}

__global__ __launch_bounds__(256) void decoder_mma_kernel(
    const float* __restrict__ dec_in, const float* __restrict__ s_in,
    const float* __restrict__ enc,    const float* __restrict__ W_attn,
    const float* __restrict__ b_attn, const float* __restrict__ v_attn,
    const float* __restrict__ W_emb,  const float* __restrict__ b_emb,
    const float* __restrict__ W_ih,   const float* __restrict__ W_hh,
    const float* __restrict__ b_ih,   const float* __restrict__ b_hh,
    const float* __restrict__ W_fc,   const float* __restrict__ b_fc,
    float* __restrict__ out, int write_h)
{
    __shared__ uint32_t As[128 * ASTR];    // enc chunk, tf32 bits, row-major
    __shared__ uint32_t Bs[64 * BSTR];     // We^T (k x j), tf32 bits
    __shared__ float psm[128];
    __shared__ float ctxp[8][64];          // per-warp ctx partials
    __shared__ float ctxa[64];
    __shared__ float s_sm[32], pre_sm[32], v_sm2[32];
    __shared__ float gh_sm[96], gie_sm[96], emb_sm[16];
    __shared__ float red[8];
    __shared__ float lsum_sm;

    const int t    = threadIdx.x;
    const int b    = blockIdx.x;
    const int lane = t & 31;
    const int w    = t >> 5;
    const int qid  = lane >> 2;    // group id 0..7
    const int qtr  = lane & 3;     // thread-in-group 0..3

    // ---------------- init ----------------
    if (t < 32) s_sm[t] = s_in[b * 32 + t];
    if (t < 16) {
        float e = W_emb[t] * dec_in[b] + b_emb[t];
        emb_sm[t] = e > 0.f ? e : 0.f;
    }
    // stage B = We^T: Bs[k][j] = W_attn[j*96 + 32 + k]
    for (int idx = t; idx < 2048; idx += 256) {
        int j = idx >> 6, k = idx & 63;
        Bs[k * BSTR + j] = f2tf32(W_attn[j * 96 + 32 + k]);
    }
    __syncthreads();

    if (t < 32) {
        float a = b_attn[t];
        #pragma unroll
        for (int m = 0; m < 32; ++m) a += W_attn[t * 96 + m] * s_sm[m];
        pre_sm[t] = a;
        v_sm2[t]  = v_attn[t];
    } else if (t < 128) {
        int g = t - 32;
        float a = b_hh[g];
        #pragma unroll
        for (int m = 0; m < 32; ++m) a += W_hh[g * 32 + m] * s_sm[m];
        gh_sm[g] = a;
    } else if (t < 224) {
        int g = t - 128;
        float a = b_ih[g];
        #pragma unroll
        for (int m = 0; m < 16; ++m) a += W_ih[g * 80 + m] * emb_sm[m];
        gie_sm[g] = a;
    }
    __syncthreads();

    // B fragments in registers (constant across chunks):
    // b0 = B[8ks+qtr][8nt+qid], b1 = B[8ks+4+qtr][8nt+qid]
    uint32_t Br[4][8][2];
    #pragma unroll
    for (int nt = 0; nt < 4; ++nt)
        #pragma unroll
        for (int ks = 0; ks < 8; ++ks) {
            Br[nt][ks][0] = Bs[(8 * ks + qtr) * BSTR + 8 * nt + qid];
            Br[nt][ks][1] = Bs[(8 * ks + 4 + qtr) * BSTR + 8 * nt + qid];
        }
    // per-thread pre/v for owned cols: c = nt*8 + 2*qtr (+1)
    float preR[4][2], vR[4][2];
    #pragma unroll
    for (int nt = 0; nt < 4; ++nt) {
        int c = nt * 8 + 2 * qtr;
        preR[nt][0] = pre_sm[c];     preR[nt][1] = pre_sm[c + 1];
        vR[nt][0]   = v_sm2[c];      vR[nt][1]   = v_sm2[c + 1];
    }

    const int sg = t >> 3;   // 0..31 half-row group
    const int si = t & 7;    // 16-B segment
    const int m0 = w * 16;   // warp's row slab
    const uint32_t* aptr = &As[(m0 + qid) * ASTR + qtr];

    float cacc0 = 0.f, cacc1 = 0.f, l_acc = 0.f;

    // ---------------- chunk loop ----------------
    for (int ch = 0; ch < 4; ++ch) {
        __syncthreads();   // prior ctx reads of As done

        // stage enc chunk (128 x 64), coalesced 128-B half-rows, cvt to tf32
        #pragma unroll
        for (int it = 0; it < 8; ++it) {
            int hr  = it * 32 + sg;
            int row = hr >> 1;
            int half = hr & 1;
            const float4 v4 = *(const float4*)(
                enc + ((size_t)(ch * 128 + row) * BB + b) * 64 + half * 32 + si * 4);
            uint4 u;
            u.x = f2tf32(v4.x); u.y = f2tf32(v4.y);
            u.z = f2tf32(v4.z); u.w = f2tf32(v4.w);
            *(uint4*)&As[row * ASTR + half * 32 + si * 4] = u;
        }
        __syncthreads();

        // MMA: D[16m x 32n] per warp, K=64 in 8 steps
        float D[4][4];
        #pragma unroll
        for (int nt = 0; nt < 4; ++nt)
            #pragma unroll
            for (int i = 0; i < 4; ++i) D[nt][i] = 0.f;

        #pragma unroll
        for (int ks = 0; ks < 8; ++ks) {
            uint32_t a[4];
            a[0] = aptr[8 * ks];
            a[1] = aptr[8 * ASTR + 8 * ks];
            a[2] = aptr[8 * ks + 4];
            a[3] = aptr[8 * ASTR + 8 * ks + 4];
            #pragma unroll
            for (int nt = 0; nt < 4; ++nt) mma_tf32(D[nt], a, Br[nt][ks]);
        }

        // epilogue: logit partials in registers
        float pl0 = 0.f, pl1 = 0.f;    // rows m0+qid, m0+8+qid
        #pragma unroll
        for (int nt = 0; nt < 4; ++nt) {
            pl0 += vR[nt][0] * tanh_ap(D[nt][0] + preR[nt][0]);
            pl0 += vR[nt][1] * tanh_ap(D[nt][1] + preR[nt][1]);
            pl1 += vR[nt][0] * tanh_ap(D[nt][2] + preR[nt][0]);
            pl1 += vR[nt][1] * tanh_ap(D[nt][3] + preR[nt][1]);
        }
        // reduce across quad (lanes sharing qid)
        pl0 += __shfl_xor_sync(0xffffffffu, pl0, 1);
        pl0 += __shfl_xor_sync(0xffffffffu, pl0, 2);
        pl1 += __shfl_xor_sync(0xffffffffu, pl1, 1);
        pl1 += __shfl_xor_sync(0xffffffffu, pl1, 2);
        if (qtr == 0) {
            // |logit| <= ||v||_1 ~ 1.3 -> exp safe without max subtraction
            float p0 = __expf(pl0);
            float p1 = __expf(pl1);
            psm[m0 + qid]     = p0;
            psm[m0 + 8 + qid] = p1;
            l_acc += p0 + p1;
        }
        __syncthreads();

        // ctx accumulation: warp sweeps its 16 rows, lanes cover h = 2*lane, +1
        #pragma unroll
        for (int rr = 0; rr < 16; ++rr) {
            int row = m0 + rr;
            float ps = psm[row];
            float2 e2 = *(const float2*)&As[row * ASTR + 2 * lane];
            cacc0 += ps * e2.x;
            cacc1 += ps * e2.y;
        }
    }

    // ---------------- reductions ----------------
    ctxp[w][2 * lane]     = cacc0;
    ctxp[w][2 * lane + 1] = cacc1;
    {
        float ws = l_acc;
        #pragma unroll
        for (int off = 16; off > 0; off >>= 1)
            ws += __shfl_xor_sync(0xffffffffu, ws, off);
        if (lane == 0) red[w] = ws;
    }
    __syncthreads();
    if (t == 0)
        lsum_sm = red[0] + red[1] + red[2] + red[3] +
                  red[4] + red[5] + red[6] + red[7];
    __syncthreads();
    if (t < 64) {
        float c = 0.f;
        #pragma unroll
        for (int ww = 0; ww < 8; ++ww) c += ctxp[ww][t];
        ctxa[t] = c / lsum_sm;
    }
    __syncthreads();

    // ---------------- GRU + fc (warp 0) ----------------
    if (w == 0) {
        int j = lane;
        float gir = gie_sm[j], giz = gie_sm[32 + j], gin = gie_sm[64 + j];
        const float* wr = W_ih + j        * 80 + 16;
        const float* wz = W_ih + (32 + j) * 80 + 16;
        const float* wn = W_ih + (64 + j) * 80 + 16;
        #pragma unroll 8
        for (int k2 = 0; k2 < 64; ++k2) {
            float c = ctxa[k2];
            gir += wr[k2] * c;
            giz += wz[k2] * c;
            gin += wn[k2] * c;
        }
        float r = sigm(gir + gh_sm[j]);
        float z = sigm(giz + gh_sm[32 + j]);
        float n = tanhf(gin + r * gh_sm[64 + j]);
        float h = (1.f - z) * n + z * s_sm[j];
        if (write_h) out[BB + b * 32 + j] = h;

        float contrib = h * W_fc[j]
                      + ctxa[2 * j]     * W_fc[32 + 2 * j]
                      + ctxa[2 * j + 1] * W_fc[33 + 2 * j];
        if (j < 16) contrib += emb_sm[j] * W_fc[96 + j];
        #pragma unroll
        for (int off = 16; off > 0; off >>= 1)
            contrib += __shfl_xor_sync(0xffffffffu, contrib, off);
        if (j == 0) out[b] = contrib + b_fc[0];
    }
}

extern "C" void kernel_launch(void* const* d_in, const int* in_sizes, int n_in,
                              void* d_out, int out_size) {
    const float* dec_in = (const float*)d_in[0];
    const float* s_in   = (const float*)d_in[1];
    const float* enc    = (const float*)d_in[2];
    const float* W_attn = (const float*)d_in[3];
    const float* b_attn = (const float*)d_in[4];
    const float* v_attn = (const float*)d_in[5];
    const float* W_emb  = (const float*)d_in[6];
    const float* b_emb  = (const float*)d_in[7];
    const float* W_ih   = (const float*)d_in[8];
    const float* W_hh   = (const float*)d_in[9];
    const float* b_ih   = (const float*)d_in[10];
    const float* b_hh   = (const float*)d_in[11];
    const float* W_fc   = (const float*)d_in[12];
    const float* b_fc   = (const float*)d_in[13];

    int write_h = (out_size >= BB * 33) ? 1 : 0;
    decoder_mma_kernel<<<BB, 256>>>(dec_in, s_in, enc, W_attn, b_attn, v_attn,
                                    W_emb, b_emb, W_ih, W_hh, b_ih, b_hh,
                                    W_fc, b_fc, (float*)d_out, write_h);
}